// round 7
// baseline (speedup 1.0000x reference)
#include <cuda_runtime.h>
#include <cstdint>

#define F_DIM    48
#define CHUNKS   12            // 48 floats = 12 float4 per node
#define N_NODES  100000
#define N_EDGES  1600000

#define SCAN_TPB   1024
#define SCAN_ELEMS (N_NODES + 1)                                // 100001
#define SCAN_NBLK  ((SCAN_ELEMS + SCAN_TPB - 1) / SCAN_TPB)     // 98

// ---------------------------------------------------------------------------
// Scratch (__device__ globals — no allocation)
// ---------------------------------------------------------------------------
__device__ int  g_count[N_NODES + 1];     // histogram -> CSR offsets
__device__ int  g_rank[N_EDGES];          // rank of edge within its row
__device__ int  g_blocksums[SCAN_NBLK];
__device__ int2 g_edge[N_EDGES];          // row-sorted {col, val-bits}

// ---------------------------------------------------------------------------
// 1. histogram + rank capture, 4 edges/thread (vectorized meta loads).
//    Atomic return is stored, never consumed -> latency hidden.
//    nE is a multiple of 4 (1.6M); guarded anyway.
// ---------------------------------------------------------------------------
__global__ __launch_bounds__(256)
void hist_kernel(const int* __restrict__ rows, int nE) {
    int q = blockIdx.x * blockDim.x + threadIdx.x;   // quad index
    int e = q * 4;
    if (e + 3 < nE) {
        int4 r = *reinterpret_cast<const int4*>(rows + e);
        int k0 = atomicAdd(&g_count[r.x + 1], 1);
        int k1 = atomicAdd(&g_count[r.y + 1], 1);
        int k2 = atomicAdd(&g_count[r.z + 1], 1);
        int k3 = atomicAdd(&g_count[r.w + 1], 1);
        *reinterpret_cast<int4*>(g_rank + e) = make_int4(k0, k1, k2, k3);
    } else {
        for (; e < nE; e++)
            g_rank[e] = atomicAdd(&g_count[__ldg(rows + e) + 1], 1);
    }
}

// ---------------------------------------------------------------------------
// 2a. block-local inclusive scan (1024 elems/block) + block sums
// ---------------------------------------------------------------------------
__global__ __launch_bounds__(SCAN_TPB)
void scan1_kernel() {
    __shared__ int buf[2][SCAN_TPB];
    int t = threadIdx.x;
    int idx = blockIdx.x * SCAN_TPB + t;
    int v = (idx < SCAN_ELEMS) ? g_count[idx] : 0;
    int src = 0;
    buf[0][t] = v;
    __syncthreads();
    #pragma unroll
    for (int off = 1; off < SCAN_TPB; off <<= 1) {
        int val = buf[src][t];
        if (t >= off) val += buf[src][t - off];
        buf[src ^ 1][t] = val;
        src ^= 1;
        __syncthreads();
    }
    if (idx < SCAN_ELEMS) g_count[idx] = buf[src][t];
    if (t == SCAN_TPB - 1) g_blocksums[blockIdx.x] = buf[src][t];
}

// ---------------------------------------------------------------------------
// 2b. fixup: add prefix of block sums (uniform broadcast loop, <=97 iters)
// ---------------------------------------------------------------------------
__global__ __launch_bounds__(SCAN_TPB)
void scan2_kernel() {
    int t = threadIdx.x;
    int idx = blockIdx.x * SCAN_TPB + t;
    if (idx >= SCAN_ELEMS || blockIdx.x == 0) return;

    int base = 0;
    for (int b = 0; b < blockIdx.x; b++) base += __ldg(&g_blocksums[b]);
    g_count[idx] += base;
}

// ---------------------------------------------------------------------------
// 3. reorder: atomic-free, 4 edges/thread. Vector loads of all meta, then
//    4 INDEPENDENT random g_count loads + 4 independent 8B scatter stores.
// ---------------------------------------------------------------------------
__global__ __launch_bounds__(256)
void reorder_kernel(const int*   __restrict__ rows,
                    const int*   __restrict__ cols,
                    const float* __restrict__ vals, int nE) {
    int q = blockIdx.x * blockDim.x + threadIdx.x;
    int e = q * 4;
    if (e + 3 < nE) {
        int4   r  = *reinterpret_cast<const int4*>(rows + e);
        int4   cc = *reinterpret_cast<const int4*>(cols + e);
        float4 vv = *reinterpret_cast<const float4*>(vals + e);
        int4   kk = *reinterpret_cast<const int4*>(g_rank + e);
        // 4 independent random loads in flight
        int b0 = __ldg(&g_count[r.x]);
        int b1 = __ldg(&g_count[r.y]);
        int b2 = __ldg(&g_count[r.z]);
        int b3 = __ldg(&g_count[r.w]);
        g_edge[b0 + kk.x] = make_int2(cc.x, __float_as_int(vv.x));
        g_edge[b1 + kk.y] = make_int2(cc.y, __float_as_int(vv.y));
        g_edge[b2 + kk.z] = make_int2(cc.z, __float_as_int(vv.z));
        g_edge[b3 + kk.w] = make_int2(cc.w, __float_as_int(vv.w));
    } else {
        for (; e < nE; e++) {
            int p = __ldg(&g_count[__ldg(rows + e)]) + __ldg(&g_rank[e]);
            g_edge[p] = make_int2(__ldg(cols + e),
                                  __float_as_int(__ldg(vals + e)));
        }
    }
}

// ---------------------------------------------------------------------------
// 4. gather: 12 lanes per node, register accumulation, w applied at the end,
//    single output write. No atomics. 4-deep unroll for MLP.
// ---------------------------------------------------------------------------
__global__ __launch_bounds__(256)
void gather_kernel(const float*  __restrict__ x,
                   const float4* __restrict__ w4,
                   float4*       __restrict__ out4) {
    int gid = blockIdx.x * blockDim.x + threadIdx.x;
    int node = gid / CHUNKS;
    int c = gid - node * CHUNKS;
    if (node >= N_NODES) return;

    const int start = __ldg(&g_count[node]);
    const int end   = __ldg(&g_count[node + 1]);

    float4 acc = make_float4(0.f, 0.f, 0.f, 0.f);
    int e = start;
    for (; e + 3 < end; e += 4) {
        int2 m0 = __ldg(g_edge + e + 0);
        int2 m1 = __ldg(g_edge + e + 1);
        int2 m2 = __ldg(g_edge + e + 2);
        int2 m3 = __ldg(g_edge + e + 3);
        float4 a0 = *reinterpret_cast<const float4*>(x + (size_t)m0.x * F_DIM + c * 4);
        float4 a1 = *reinterpret_cast<const float4*>(x + (size_t)m1.x * F_DIM + c * 4);
        float4 a2 = *reinterpret_cast<const float4*>(x + (size_t)m2.x * F_DIM + c * 4);
        float4 a3 = *reinterpret_cast<const float4*>(x + (size_t)m3.x * F_DIM + c * 4);
        float v0 = __int_as_float(m0.y), v1 = __int_as_float(m1.y);
        float v2 = __int_as_float(m2.y), v3 = __int_as_float(m3.y);
        acc.x += v0 * a0.x + v1 * a1.x + v2 * a2.x + v3 * a3.x;
        acc.y += v0 * a0.y + v1 * a1.y + v2 * a2.y + v3 * a3.y;
        acc.z += v0 * a0.z + v1 * a1.z + v2 * a2.z + v3 * a3.z;
        acc.w += v0 * a0.w + v1 * a1.w + v2 * a2.w + v3 * a3.w;
    }
    for (; e < end; e++) {
        int2 m = __ldg(g_edge + e);
        float4 a = *reinterpret_cast<const float4*>(x + (size_t)m.x * F_DIM + c * 4);
        float v = __int_as_float(m.y);
        acc.x += v * a.x;
        acc.y += v * a.y;
        acc.z += v * a.z;
        acc.w += v * a.w;
    }

    float4 wv = __ldg(w4 + c);
    acc.x *= wv.x; acc.y *= wv.y; acc.z *= wv.z; acc.w *= wv.w;

    out4[(size_t)node * CHUNKS + c] = acc;
}

// ---------------------------------------------------------------------------
// Launch
// Inputs: 0 x[1,100000,48] f32 | 1 w[1,48] f32 | 2 rows[1.6M] i32
//         3 cols[1.6M] i32     | 4 vals[1.6M] f32
// Output: f32 [100000, 48]
// ---------------------------------------------------------------------------
extern "C" void kernel_launch(void* const* d_in, const int* in_sizes, int n_in,
                              void* d_out, int out_size) {
    const float* x    = (const float*)d_in[0];
    const float* w    = (const float*)d_in[1];
    const int*   rows = (const int*)  d_in[2];
    const int*   cols = (const int*)  d_in[3];
    const float* vals = (const float*)d_in[4];
    float*       out  = (float*)d_out;

    const int nE = in_sizes[2];

    // 0. zero histogram (capturable async memset; no allocation)
    void* count_ptr = nullptr;
    cudaGetSymbolAddress(&count_ptr, g_count);
    cudaMemsetAsync(count_ptr, 0, (N_NODES + 1) * sizeof(int), 0);

    // 1. histogram + rank (4 edges/thread)
    {
        int nq = (nE + 3) / 4;
        hist_kernel<<<(nq + 255) / 256, 256>>>(rows, nE);
    }
    // 2. scan
    scan1_kernel<<<SCAN_NBLK, SCAN_TPB>>>();
    scan2_kernel<<<SCAN_NBLK, SCAN_TPB>>>();
    // 3. reorder (atomic-free, 4 edges/thread)
    {
        int nq = (nE + 3) / 4;
        reorder_kernel<<<(nq + 255) / 256, 256>>>(rows, cols, vals, nE);
    }
    // 4. gather
    {
        int n = N_NODES * CHUNKS;
        gather_kernel<<<(n + 255) / 256, 256>>>(x, (const float4*)w,
                                                (float4*)out);
    }
}